// round 12
// baseline (speedup 1.0000x reference)
#include <cuda_runtime.h>
#include <cstdint>

#define NBOX   8192
#define CLS    81
#define NPAD   300
#define NWORDS (NBOX / 32)      // 256 words per mask row
#define NCH    (NBOX / 64)      // 128 scan chunks of 64 boxes

// ------------------------- device scratch (static, no allocs) --------------
__device__ float4             g_selv[NBOX];     // decoded boxes (orig order)
__device__ unsigned long long g_key[NBOX];      // composite sort keys
__device__ float4             g_sbox[NBOX];     // boxes in sorted order
__device__ float              g_sarea[NBOX];    // areas in sorted order
__device__ int                g_orig[NBOX];     // sorted pos -> original idx
__device__ unsigned           g_masks[(size_t)NBOX * NWORDS]; // sorted-space IoU>0.5
__device__ int                g_probe[512];     // probe-only scratch

// ---------------------------------------------------------------------------
// Kernel 1: per-row argmax / max + bbox decode + sort-key build. 1 warp/row.
// ---------------------------------------------------------------------------
__global__ void decode_kernel(const float* __restrict__ meta,
                              const float* __restrict__ deltas,
                              const float* __restrict__ proposals,
                              const float* __restrict__ scores) {
    int row  = (int)((blockIdx.x * blockDim.x + threadIdx.x) >> 5);
    int lane = threadIdx.x & 31;
    if (row >= NBOX) return;

    const float* srow = scores + (size_t)row * CLS;
    float best = -1.0f;
    int   bidx = 0x7FFFFFFF;
    float ms   = -1.0f;
    for (int j = lane; j < CLS; j += 32) {
        float v = srow[j];
        if (v > best) { best = v; bidx = j; }
        if (j >= 1) ms = fmaxf(ms, v);
    }
    #pragma unroll
    for (int off = 16; off; off >>= 1) {
        float ov = __shfl_down_sync(0xffffffffu, best, off);
        int   oi = __shfl_down_sync(0xffffffffu, bidx, off);
        float om = __shfl_down_sync(0xffffffffu, ms,   off);
        if (ov > best || (ov == best && oi < bidx)) { best = ov; bidx = oi; }
        ms = fmaxf(ms, om);
    }

    if (lane == 0) {
        float scale = meta[2];
        const float* p = proposals + (size_t)row * 4;
        float x1 = p[0] / scale, y1 = p[1] / scale;
        float x2 = p[2] / scale, y2 = p[3] / scale;
        float w  = x2 - x1 + 1.0f, h = y2 - y1 + 1.0f;
        float cx = x1 + 0.5f * w,  cy = y1 + 0.5f * h;

        const float* d = deltas + (size_t)row * (4 * CLS) + 4 * bidx;
        float pcx = d[0] * w + cx;
        float pcy = d[1] * h + cy;
        float pw  = expf(d[2]) * w;
        float ph  = expf(d[3]) * h;

        float W1 = meta[1] - 1.0f;
        float H1 = meta[0] - 1.0f;
        float ox1 = fminf(fmaxf(pcx - 0.5f * pw, 0.0f), W1);
        float oy1 = fminf(fmaxf(pcy - 0.5f * ph, 0.0f), H1);
        float ox2 = fminf(fmaxf(pcx + 0.5f * pw, 0.0f), W1);
        float oy2 = fminf(fmaxf(pcy + 0.5f * ph, 0.0f), H1);

        g_selv[row] = make_float4(ox1, oy1, ox2, oy2);
        unsigned int sb = __float_as_uint(ms);   // scores >= 0 -> monotonic bits
        g_key[row] = ((unsigned long long)sb << 13) |
                     (unsigned long long)(8191 - row);   // all keys distinct
    }
}

// ---------------------------------------------------------------------------
// Kernel 2: rank-by-counting + scatter into sorted order. 256 blocks.
// ---------------------------------------------------------------------------
__global__ void __launch_bounds__(256)
rank_kernel() {
    extern __shared__ unsigned long long keys[];   // 64 KB
    const int tid = threadIdx.x;
    for (int i = tid; i < NBOX; i += 256) keys[i] = g_key[i];
    __syncthreads();

    const int warp = tid >> 5, lane = tid & 31;
    const int row0 = blockIdx.x * 32 + warp * 4;

    unsigned long long rk0 = keys[row0 + 0];
    unsigned long long rk1 = keys[row0 + 1];
    unsigned long long rk2 = keys[row0 + 2];
    unsigned long long rk3 = keys[row0 + 3];
    int c0 = 0, c1 = 0, c2 = 0, c3 = 0;

    #pragma unroll 4
    for (int c = lane; c < NBOX; c += 32) {
        unsigned long long kc = keys[c];
        c0 += (kc > rk0);
        c1 += (kc > rk1);
        c2 += (kc > rk2);
        c3 += (kc > rk3);
    }
    #pragma unroll
    for (int off = 16; off; off >>= 1) {
        c0 += __shfl_down_sync(0xffffffffu, c0, off);
        c1 += __shfl_down_sync(0xffffffffu, c1, off);
        c2 += __shfl_down_sync(0xffffffffu, c2, off);
        c3 += __shfl_down_sync(0xffffffffu, c3, off);
    }
    if (lane == 0) {
        int rr[4] = {c0, c1, c2, c3};
        #pragma unroll
        for (int q = 0; q < 4; q++) {
            int i = row0 + q, r = rr[q];
            float4 b = g_selv[i];
            g_sbox[r]  = b;
            g_sarea[r] = fmaxf(b.z - b.x, 0.0f) * fmaxf(b.w - b.y, 0.0f);
            g_orig[r]  = i;
        }
    }
}

// ---------------------------------------------------------------------------
// Kernel 3: sorted-space IoU>0.5 bitmask, upper triangle only.
// ---------------------------------------------------------------------------
__global__ void __launch_bounds__(256)
mask_kernel() {
    __shared__ float4 rbs[32];
    __shared__ float  ras[32];
    __shared__ float4 cbT[32 * 33];
    __shared__ float  caT[32 * 33];

    const int m  = blockIdx.x;
    const int rb = m & 255;
    const int cb = m >> 8;
    if (cb < (rb >> 5)) return;

    const int rowbase = rb * 32;
    const int colbase = cb * 1024;
    const int tid = threadIdx.x;

    if (tid < 32) {
        rbs[tid] = g_sbox[rowbase + tid];
        ras[tid] = g_sarea[rowbase + tid];
    }
    for (int jj = tid; jj < 1024; jj += 256) {
        int w = jj >> 5, bb = jj & 31;
        cbT[bb * 33 + w] = g_sbox[colbase + jj];
        caT[bb * 33 + w] = g_sarea[colbase + jj];
    }
    __syncthreads();

    const int r0 = tid >> 5;
    const int w  = tid & 31;
    float4 bi[4];
    float  si[4];
    #pragma unroll
    for (int k = 0; k < 4; k++) {
        bi[k] = rbs[r0 + 8 * k];
        si[k] = ras[r0 + 8 * k] + 1e-8f;
    }
    unsigned bits0 = 0, bits1 = 0, bits2 = 0, bits3 = 0;

    #pragma unroll
    for (int b = 0; b < 32; b++) {
        float4 bj = cbT[b * 33 + w];
        float  aj = caT[b * 33 + w];
        #pragma unroll
        for (int k = 0; k < 4; k++) {
            float xx1 = fmaxf(bi[k].x, bj.x), yy1 = fmaxf(bi[k].y, bj.y);
            float xx2 = fminf(bi[k].z, bj.z), yy2 = fminf(bi[k].w, bj.w);
            float iw  = fmaxf(xx2 - xx1, 0.0f);
            float ih  = fmaxf(yy2 - yy1, 0.0f);
            float inter = iw * ih;
            unsigned p = (3.0f * inter > si[k] + aj) ? (1u << b) : 0u;
            if (k == 0) bits0 |= p;
            else if (k == 1) bits1 |= p;
            else if (k == 2) bits2 |= p;
            else bits3 |= p;
        }
    }
    size_t base = (size_t)rowbase * NWORDS + (size_t)cb * 32 + w;
    g_masks[base + (size_t)(r0 +  0) * NWORDS] = bits0;
    g_masks[base + (size_t)(r0 +  8) * NWORDS] = bits1;
    g_masks[base + (size_t)(r0 + 16) * NWORDS] = bits2;
    g_masks[base + (size_t)(r0 + 24) * NWORDS] = bits3;
}

// ---------------------------------------------------------------------------
// PROBE kernel: exact clone of scan_kernel, but keep-row global gathers are
// replaced by smem reads (identical loop/control structure). Isolates the
// global-gather contribution. Writes only to g_probe scratch.
// ---------------------------------------------------------------------------
__global__ void __launch_bounds__(256)
probe_kernel() {
    __shared__ unsigned           sup_s[NWORDS];
    __shared__ unsigned long long kbuf64[2];
    __shared__ int                kcnt[2];
    __shared__ int                s_keep[NPAD];
    __shared__ unsigned long long confb[2][64];
    __shared__ unsigned long long n1b[2][64];
    __shared__ unsigned long long n2b[2][64];
    __shared__ unsigned           dummyw[256];   // replaces gather source

    const int tid = threadIdx.x;
    sup_s[tid] = 0u;
    dummyw[tid] = (unsigned)(g_key[tid] >> (tid & 7));   // runtime, non-foldable
    if (tid == 0) { kbuf64[0] = kbuf64[1] = 0ull; kcnt[0] = kcnt[1] = 0; }

    if (tid >= 32 && tid < 224) {
        int e = tid - 32, row = e / 3, f = e - row * 3;
        const unsigned* r = &g_masks[(size_t)row * NWORDS];
        int w = 2 * f;
        unsigned long long v = (unsigned long long)__ldg(r + w) |
                               ((unsigned long long)__ldg(r + w + 1) << 32);
        if (f == 0) confb[0][row] = v;
        else if (f == 1) n1b[0][row] = v;
        else n2b[0][row] = v;
    }
    __syncthreads();

    unsigned long long supfix = 0ull, carry = 0ull;
    unsigned b1a = 0u, b1b = 0u, b2a = 0u, b2b = 0u;
    const int w0 = tid - 32;
    const int w1 = (w0 >= 0 && w0 < 32) ? w0 + 224 : -1;
    int nk_local = 0;

    for (int c = 0; c < NCH; c++) {
        if (tid >= 32) {
            if (b2a) sup_s[w0] |= b2a;
            if (w1 >= 0 && b2b) sup_s[w1] |= b2b;
        }
        __syncthreads();
        if (c > 0 && kcnt[(c - 1) & 1] >= NPAD) break;

        if (tid == 0) {
            const int b    = c & 1;
            const int base = c * 64;
            unsigned long long sup64 =
                *(const unsigned long long*)&sup_s[2 * c];
            unsigned long long am = ~(sup64 | supfix);
            unsigned long long keepm = 0ull, n1acc = 0ull, n2acc = 0ull;
            int k2 = nk_local;
            while (am) {
                int l = __ffsll((long long)am) - 1;
                keepm |= 1ull << l;
                unsigned long long cl = confb[b][l];
                n1acc |= n1b[b][l];
                n2acc |= n2b[b][l];
                am &= ~cl;
                am &= ~(1ull << l);
                if (k2 < NPAD) s_keep[k2++] = base + l;
            }
            kbuf64[b] = keepm;
            kcnt[b]   = k2;
            nk_local  = k2;
            supfix = carry | n1acc;
            carry  = n2acc;
        } else if (tid >= 32) {
            const int cn = c + 1;
            if (cn < NCH && tid < 224) {
                int e = tid - 32, row = e / 3, f = e - row * 3;
                const unsigned* r = &g_masks[(size_t)(64 * cn + row) * NWORDS];
                int w = 2 * cn + 2 * f;
                if (w > NWORDS - 2) w = NWORDS - 2;
                unsigned long long v = (unsigned long long)__ldg(r + w) |
                                       ((unsigned long long)__ldg(r + w + 1) << 32);
                if (f == 0) confb[cn & 1][row] = v;
                else if (f == 1) n1b[cn & 1][row] = v;
                else n2b[cn & 1][row] = v;
            }
            // stage B: SAME loop structure, but loads come from smem (probe)
            unsigned a0 = 0u, a1 = 0u;
            if (c > 0) {
                unsigned long long km = kbuf64[(c - 1) & 1];
                while (km) {
                    int l = __ffsll((long long)km) - 1; km &= km - 1;
                    a0 |= dummyw[(w0 + l) & 255];
                    if (w1 >= 0) a1 |= dummyw[(w1 + l) & 255];
                }
            }
            b2a = b1a; b2b = b1b;
            b1a = a0;  b1b = a1;
        }
    }
    __syncthreads();
    const int nk = (kcnt[0] > kcnt[1]) ? kcnt[0] : kcnt[1];

    // sink everything into probe scratch (prevent DCE; never touches out/g_*)
    if (tid < 256) g_probe[tid & 255] = (int)sup_s[tid];
    if (tid == 0) {
        int acc = nk;
        for (int i = 0; i < nk && i < NPAD; i++) acc += s_keep[i];
        g_probe[256] = acc;
    }
}

// ---------------------------------------------------------------------------
// Kernel 4 (R7 exact): greedy scan, single-thread resolution over smem-staged
// operands; lag-3 keep-row suppression pipeline. Produces the real output.
// ---------------------------------------------------------------------------
__global__ void __launch_bounds__(256)
scan_kernel(const float* __restrict__ scores, float* __restrict__ out) {
    __shared__ unsigned           sup_s[NWORDS];
    __shared__ unsigned long long kbuf64[2];
    __shared__ int                kcnt[2];
    __shared__ int                s_keep[NPAD];
    __shared__ unsigned long long confb[2][64];
    __shared__ unsigned long long n1b[2][64];
    __shared__ unsigned long long n2b[2][64];

    const int tid = threadIdx.x;
    sup_s[tid] = 0u;
    if (tid == 0) { kbuf64[0] = kbuf64[1] = 0ull; kcnt[0] = kcnt[1] = 0; }

    if (tid >= 32 && tid < 224) {
        int e = tid - 32, row = e / 3, f = e - row * 3;
        const unsigned* r = &g_masks[(size_t)row * NWORDS];
        int w = 2 * f;
        unsigned long long v = (unsigned long long)__ldg(r + w) |
                               ((unsigned long long)__ldg(r + w + 1) << 32);
        if (f == 0) confb[0][row] = v;
        else if (f == 1) n1b[0][row] = v;
        else n2b[0][row] = v;
    }
    __syncthreads();

    unsigned long long supfix = 0ull, carry = 0ull;
    unsigned b1a = 0u, b1b = 0u, b2a = 0u, b2b = 0u;
    const int w0 = tid - 32;
    const int w1 = (w0 >= 0 && w0 < 32) ? w0 + 224 : -1;
    int nk_local = 0;

    for (int c = 0; c < NCH; c++) {
        if (tid >= 32) {
            if (b2a) sup_s[w0] |= b2a;
            if (w1 >= 0 && b2b) sup_s[w1] |= b2b;
        }
        __syncthreads();
        if (c > 0 && kcnt[(c - 1) & 1] >= NPAD) break;

        if (tid == 0) {
            const int b    = c & 1;
            const int base = c * 64;
            unsigned long long sup64 =
                *(const unsigned long long*)&sup_s[2 * c];
            unsigned long long am = ~(sup64 | supfix);
            unsigned long long keepm = 0ull, n1acc = 0ull, n2acc = 0ull;
            int k2 = nk_local;
            while (am) {
                int l = __ffsll((long long)am) - 1;
                keepm |= 1ull << l;
                unsigned long long cl = confb[b][l];
                n1acc |= n1b[b][l];
                n2acc |= n2b[b][l];
                am &= ~cl;
                am &= ~(1ull << l);
                if (k2 < NPAD) s_keep[k2++] = base + l;
            }
            kbuf64[b] = keepm;
            kcnt[b]   = k2;
            nk_local  = k2;
            supfix = carry | n1acc;
            carry  = n2acc;
        } else if (tid >= 32) {
            const int cn = c + 1;
            if (cn < NCH && tid < 224) {
                int e = tid - 32, row = e / 3, f = e - row * 3;
                const unsigned* r = &g_masks[(size_t)(64 * cn + row) * NWORDS];
                int w = 2 * cn + 2 * f;
                if (w > NWORDS - 2) w = NWORDS - 2;
                unsigned long long v = (unsigned long long)__ldg(r + w) |
                                       ((unsigned long long)__ldg(r + w + 1) << 32);
                if (f == 0) confb[cn & 1][row] = v;
                else if (f == 1) n1b[cn & 1][row] = v;
                else n2b[cn & 1][row] = v;
            }
            unsigned a0 = 0u, a1 = 0u;
            if (c > 0) {
                unsigned long long km = kbuf64[(c - 1) & 1];
                const size_t pb = (size_t)(c - 1) * 64;
                while (km) {
                    int l = __ffsll((long long)km) - 1; km &= km - 1;
                    const unsigned* row = &g_masks[(pb + l) * NWORDS];
                    a0 |= __ldg(row + w0);
                    if (w1 >= 0) a1 |= __ldg(row + w1);
                }
            }
            b2a = b1a; b2b = b1b;
            b1a = a0;  b1b = a1;
        }
    }
    __syncthreads();
    const int nk = (kcnt[0] > kcnt[1]) ? kcnt[0] : kcnt[1];

    for (int idx = tid; idx < NPAD * 4; idx += 256) {
        int r = idx >> 2, cc = idx & 3;
        float v = 0.0f;
        if (r < nk) {
            float4 b = g_sbox[s_keep[r]];
            v = (cc == 0) ? b.x : (cc == 1) ? b.y : (cc == 2) ? b.z : b.w;
        }
        out[idx] = v;
    }
    for (int idx = tid; idx < NPAD * CLS; idx += 256) {
        int r = idx / CLS, cc = idx - r * CLS;
        float v = 0.0f;
        if (r < nk)
            v = scores[(size_t)g_orig[s_keep[r]] * CLS + cc];
        out[NPAD * 4 + idx] = v;
    }
}

// ---------------------------------------------------------------------------
extern "C" void kernel_launch(void* const* d_in, const int* in_sizes, int n_in,
                              void* d_out, int out_size) {
    const float* meta      = (const float*)d_in[0];
    const float* deltas    = (const float*)d_in[1];
    const float* proposals = (const float*)d_in[2];
    const float* scores    = (const float*)d_in[3];
    float* out = (float*)d_out;

    decode_kernel<<<NBOX / 8, 256>>>(meta, deltas, proposals, scores);

    cudaFuncSetAttribute(rank_kernel,
                         cudaFuncAttributeMaxDynamicSharedMemorySize, 65536);
    rank_kernel<<<256, 256, 65536>>>();

    mask_kernel<<<2048, 256>>>();

    probe_kernel<<<1, 256>>>();          // measurement probe (scratch-only)

    scan_kernel<<<1, 256>>>(scores, out);
}

// round 13
// speedup vs baseline: 1.0390x; 1.0390x over previous
#include <cuda_runtime.h>
#include <cstdint>

#define NBOX   8192
#define CLS    81
#define NPAD   300
#define NWORDS (NBOX / 32)      // 256 words per mask row
#define NCH    (NBOX / 64)      // 128 scan chunks of 64 boxes

// ------------------------- device scratch (static, no allocs) --------------
__device__ float4             g_selv[NBOX];     // decoded boxes (orig order)
__device__ unsigned long long g_key[NBOX];      // composite sort keys
__device__ float4             g_sbox[NBOX];     // boxes in sorted order
__device__ float              g_sarea[NBOX];    // areas in sorted order
__device__ int                g_orig[NBOX];     // sorted pos -> original idx
__device__ unsigned           g_masks[(size_t)NBOX * NWORDS]; // sorted-space IoU>0.5

// ---------------------------------------------------------------------------
// Kernel 1: per-row argmax / max + bbox decode + sort-key build. 1 warp/row.
// ---------------------------------------------------------------------------
__global__ void decode_kernel(const float* __restrict__ meta,
                              const float* __restrict__ deltas,
                              const float* __restrict__ proposals,
                              const float* __restrict__ scores) {
    int row  = (int)((blockIdx.x * blockDim.x + threadIdx.x) >> 5);
    int lane = threadIdx.x & 31;
    if (row >= NBOX) return;

    const float* srow = scores + (size_t)row * CLS;
    float best = -1.0f;
    int   bidx = 0x7FFFFFFF;
    float ms   = -1.0f;
    for (int j = lane; j < CLS; j += 32) {
        float v = srow[j];
        if (v > best) { best = v; bidx = j; }
        if (j >= 1) ms = fmaxf(ms, v);
    }
    #pragma unroll
    for (int off = 16; off; off >>= 1) {
        float ov = __shfl_down_sync(0xffffffffu, best, off);
        int   oi = __shfl_down_sync(0xffffffffu, bidx, off);
        float om = __shfl_down_sync(0xffffffffu, ms,   off);
        if (ov > best || (ov == best && oi < bidx)) { best = ov; bidx = oi; }
        ms = fmaxf(ms, om);
    }

    if (lane == 0) {
        float scale = meta[2];
        const float* p = proposals + (size_t)row * 4;
        float x1 = p[0] / scale, y1 = p[1] / scale;
        float x2 = p[2] / scale, y2 = p[3] / scale;
        float w  = x2 - x1 + 1.0f, h = y2 - y1 + 1.0f;
        float cx = x1 + 0.5f * w,  cy = y1 + 0.5f * h;

        const float* d = deltas + (size_t)row * (4 * CLS) + 4 * bidx;
        float pcx = d[0] * w + cx;
        float pcy = d[1] * h + cy;
        float pw  = expf(d[2]) * w;
        float ph  = expf(d[3]) * h;

        float W1 = meta[1] - 1.0f;
        float H1 = meta[0] - 1.0f;
        float ox1 = fminf(fmaxf(pcx - 0.5f * pw, 0.0f), W1);
        float oy1 = fminf(fmaxf(pcy - 0.5f * ph, 0.0f), H1);
        float ox2 = fminf(fmaxf(pcx + 0.5f * pw, 0.0f), W1);
        float oy2 = fminf(fmaxf(pcy + 0.5f * ph, 0.0f), H1);

        g_selv[row] = make_float4(ox1, oy1, ox2, oy2);
        unsigned int sb = __float_as_uint(ms);   // scores >= 0 -> monotonic bits
        g_key[row] = ((unsigned long long)sb << 13) |
                     (unsigned long long)(8191 - row);   // all keys distinct
    }
}

// ---------------------------------------------------------------------------
// Kernel 2: rank-by-counting + scatter into sorted order. 256 blocks.
// ---------------------------------------------------------------------------
__global__ void __launch_bounds__(256)
rank_kernel() {
    extern __shared__ unsigned long long keys[];   // 64 KB
    const int tid = threadIdx.x;
    for (int i = tid; i < NBOX; i += 256) keys[i] = g_key[i];
    __syncthreads();

    const int warp = tid >> 5, lane = tid & 31;
    const int row0 = blockIdx.x * 32 + warp * 4;

    unsigned long long rk0 = keys[row0 + 0];
    unsigned long long rk1 = keys[row0 + 1];
    unsigned long long rk2 = keys[row0 + 2];
    unsigned long long rk3 = keys[row0 + 3];
    int c0 = 0, c1 = 0, c2 = 0, c3 = 0;

    #pragma unroll 4
    for (int c = lane; c < NBOX; c += 32) {
        unsigned long long kc = keys[c];
        c0 += (kc > rk0);
        c1 += (kc > rk1);
        c2 += (kc > rk2);
        c3 += (kc > rk3);
    }
    #pragma unroll
    for (int off = 16; off; off >>= 1) {
        c0 += __shfl_down_sync(0xffffffffu, c0, off);
        c1 += __shfl_down_sync(0xffffffffu, c1, off);
        c2 += __shfl_down_sync(0xffffffffu, c2, off);
        c3 += __shfl_down_sync(0xffffffffu, c3, off);
    }
    if (lane == 0) {
        int rr[4] = {c0, c1, c2, c3};
        #pragma unroll
        for (int q = 0; q < 4; q++) {
            int i = row0 + q, r = rr[q];
            float4 b = g_selv[i];
            g_sbox[r]  = b;
            g_sarea[r] = fmaxf(b.z - b.x, 0.0f) * fmaxf(b.w - b.y, 0.0f);
            g_orig[r]  = i;
        }
    }
}

// ---------------------------------------------------------------------------
// Kernel 3: sorted-space IoU>0.5 bitmask, upper-triangle tiles only (1152).
// ---------------------------------------------------------------------------
__constant__ int c_prefix[9] = {0, 256, 480, 672, 832, 960, 1056, 1120, 1152};

__global__ void __launch_bounds__(256)
mask_kernel() {
    __shared__ float4 rbs[32];
    __shared__ float  ras[32];
    __shared__ float4 cbT[32 * 33];
    __shared__ float  caT[32 * 33];

    const int t = blockIdx.x;
    int g = 0;
    #pragma unroll
    for (int h = 1; h < 8; h++) g += (t >= c_prefix[h]);
    const int tp   = t - c_prefix[g];
    const int span = 8 - g;
    const int r    = tp / span;
    const int rb   = g * 32 + r;
    const int cb   = g + (tp - r * span);

    const int rowbase = rb * 32;
    const int colbase = cb * 1024;
    const int tid = threadIdx.x;

    if (tid < 32) {
        rbs[tid] = g_sbox[rowbase + tid];
        ras[tid] = g_sarea[rowbase + tid];
    }
    for (int jj = tid; jj < 1024; jj += 256) {
        int w = jj >> 5, bb = jj & 31;
        cbT[bb * 33 + w] = g_sbox[colbase + jj];
        caT[bb * 33 + w] = g_sarea[colbase + jj];
    }
    __syncthreads();

    const int r0 = tid >> 5;
    const int w  = tid & 31;
    float4 bi[4];
    float  si[4];
    #pragma unroll
    for (int k = 0; k < 4; k++) {
        bi[k] = rbs[r0 + 8 * k];
        si[k] = ras[r0 + 8 * k] + 1e-8f;
    }
    unsigned bits0 = 0, bits1 = 0, bits2 = 0, bits3 = 0;

    #pragma unroll
    for (int b = 0; b < 32; b++) {
        float4 bj = cbT[b * 33 + w];
        float  aj = caT[b * 33 + w];
        #pragma unroll
        for (int k = 0; k < 4; k++) {
            float xx1 = fmaxf(bi[k].x, bj.x), yy1 = fmaxf(bi[k].y, bj.y);
            float xx2 = fminf(bi[k].z, bj.z), yy2 = fminf(bi[k].w, bj.w);
            float iw  = fmaxf(xx2 - xx1, 0.0f);
            float ih  = fmaxf(yy2 - yy1, 0.0f);
            float inter = iw * ih;
            unsigned p = (3.0f * inter > si[k] + aj) ? (1u << b) : 0u;
            if (k == 0) bits0 |= p;
            else if (k == 1) bits1 |= p;
            else if (k == 2) bits2 |= p;
            else bits3 |= p;
        }
    }
    size_t base = (size_t)rowbase * NWORDS + (size_t)cb * 32 + w;
    g_masks[base + (size_t)(r0 +  0) * NWORDS] = bits0;
    g_masks[base + (size_t)(r0 +  8) * NWORDS] = bits1;
    g_masks[base + (size_t)(r0 + 16) * NWORDS] = bits2;
    g_masks[base + (size_t)(r0 + 24) * NWORDS] = bits3;
}

// ---------------------------------------------------------------------------
// Kernel 4: single-warp barrier-free greedy scan + 256-thread output.
//  warp 0 owns sup_s[256] (8 words/lane); conf diag-words prefetched one
//  chunk ahead into registers; keeps suppress via 8 coalesced LDG.32/lane.
//  NO __syncthreads in the loop — ordering via scoreboard + __syncwarp.
// ---------------------------------------------------------------------------
__global__ void __launch_bounds__(256)
scan_kernel(const float* __restrict__ scores, float* __restrict__ out) {
    __shared__ unsigned sup_s[NWORDS];
    __shared__ int      s_keep[NPAD];
    __shared__ int      s_nk;

    const int tid  = threadIdx.x;
    const int lane = tid & 31;

    if (tid < 32) {
        // zero the suppression bitmap (8 words per lane)
        #pragma unroll
        for (int q = 0; q < 8; q++) sup_s[q * 32 + lane] = 0u;
        __syncwarp();

        const unsigned long long* m64 = (const unsigned long long*)g_masks;
        // conf diag u64 for chunk 0: rows lane / lane+32, u64-word index 0
        unsigned long long confA = __ldg(m64 + (size_t)lane * 128);
        unsigned long long confB = __ldg(m64 + (size_t)(lane + 32) * 128);
        int kept = 0;

        for (int c = 0; c < NCH; c++) {
            // availability for chunk c (words 2c, 2c+1; smem broadcast)
            unsigned long long am =
                ~((unsigned long long)sup_s[2 * c] |
                  ((unsigned long long)sup_s[2 * c + 1] << 32));

            // prefetch next chunk's conf (independent; hidden)
            unsigned long long nA = 0ull, nB = 0ull;
            if (c + 1 < NCH) {
                nA = __ldg(m64 + (size_t)(64 * (c + 1) + lane) * 128 + (c + 1));
                nB = __ldg(m64 + (size_t)(64 * (c + 1) + lane + 32) * 128 + (c + 1));
            }

            // uniform resolution (identical am on all lanes)
            unsigned long long keepm = 0ull;
            while (am) {
                int l = __ffsll((long long)am) - 1;
                keepm |= 1ull << l;
                unsigned long long cl = (l < 32)
                    ? __shfl_sync(0xffffffffu, confA, l)
                    : __shfl_sync(0xffffffffu, confB, l - 32);
                am &= ~cl;
                am &= ~(1ull << l);
                if (kept < NPAD) {
                    if (lane == 0) s_keep[kept] = c * 64 + l;
                    kept++;
                }
            }
            if (kept >= NPAD) break;

            // suppression: OR kept rows into owned words (coalesced LDGs)
            if (keepm) {
                unsigned acc0 = 0, acc1 = 0, acc2 = 0, acc3 = 0;
                unsigned acc4 = 0, acc5 = 0, acc6 = 0, acc7 = 0;
                unsigned long long km = keepm;
                while (km) {
                    int l = __ffsll((long long)km) - 1; km &= km - 1;
                    const unsigned* row =
                        g_masks + (size_t)(c * 64 + l) * NWORDS + lane;
                    acc0 |= __ldg(row +   0); acc1 |= __ldg(row +  32);
                    acc2 |= __ldg(row +  64); acc3 |= __ldg(row +  96);
                    acc4 |= __ldg(row + 128); acc5 |= __ldg(row + 160);
                    acc6 |= __ldg(row + 192); acc7 |= __ldg(row + 224);
                }
                sup_s[lane +   0] |= acc0;  sup_s[lane +  32] |= acc1;
                sup_s[lane +  64] |= acc2;  sup_s[lane +  96] |= acc3;
                sup_s[lane + 128] |= acc4;  sup_s[lane + 160] |= acc5;
                sup_s[lane + 192] |= acc6;  sup_s[lane + 224] |= acc7;
                __syncwarp();
            }
            confA = nA; confB = nB;
        }
        if (lane == 0) s_nk = kept;
    }
    __syncthreads();           // warps 1-7 wake up here
    const int nk = s_nk;

    // ---- outputs: boxes (300*4) then scores (300*81); zero invalid rows ----
    for (int idx = tid; idx < NPAD * 4; idx += 256) {
        int r = idx >> 2, cc = idx & 3;
        float v = 0.0f;
        if (r < nk) {
            float4 b = g_sbox[s_keep[r]];
            v = (cc == 0) ? b.x : (cc == 1) ? b.y : (cc == 2) ? b.z : b.w;
        }
        out[idx] = v;
    }
    for (int idx = tid; idx < NPAD * CLS; idx += 256) {
        int r = idx / CLS, cc = idx - r * CLS;
        float v = 0.0f;
        if (r < nk)
            v = scores[(size_t)g_orig[s_keep[r]] * CLS + cc];
        out[NPAD * 4 + idx] = v;
    }
}

// ---------------------------------------------------------------------------
extern "C" void kernel_launch(void* const* d_in, const int* in_sizes, int n_in,
                              void* d_out, int out_size) {
    const float* meta      = (const float*)d_in[0];
    const float* deltas    = (const float*)d_in[1];
    const float* proposals = (const float*)d_in[2];
    const float* scores    = (const float*)d_in[3];
    float* out = (float*)d_out;

    decode_kernel<<<NBOX / 8, 256>>>(meta, deltas, proposals, scores);

    cudaFuncSetAttribute(rank_kernel,
                         cudaFuncAttributeMaxDynamicSharedMemorySize, 65536);
    rank_kernel<<<256, 256, 65536>>>();

    mask_kernel<<<1152, 256>>>();

    scan_kernel<<<1, 256>>>(scores, out);
}

// round 14
// speedup vs baseline: 1.9076x; 1.8360x over previous
#include <cuda_runtime.h>
#include <cstdint>

#define NBOX   8192
#define CLS    81
#define NPAD   300
#define NWORDS (NBOX / 32)      // 256 words per mask row
#define NCH    (NBOX / 64)      // 128 scan chunks of 64 boxes
#define MAXK   6                // staged keep rows per chunk (overflow -> direct)

// ------------------------- device scratch (static, no allocs) --------------
__device__ float4             g_selv[NBOX];     // decoded boxes (orig order)
__device__ unsigned long long g_key[NBOX];      // composite sort keys
__device__ float4             g_sbox[NBOX];     // boxes in sorted order
__device__ float              g_sarea[NBOX];    // areas in sorted order
__device__ int                g_orig[NBOX];     // sorted pos -> original idx
__device__ unsigned           g_masks[(size_t)NBOX * NWORDS]; // sorted-space IoU>0.5

// ------------------------- cp.async helpers --------------------------------
__device__ __forceinline__ void cp_async8(void* smem_dst, const void* gmem_src) {
    unsigned saddr = (unsigned)__cvta_generic_to_shared(smem_dst);
    asm volatile("cp.async.ca.shared.global [%0], [%1], 8;\n"
                 :: "r"(saddr), "l"(gmem_src));
}
__device__ __forceinline__ void cp_async4(void* smem_dst, const void* gmem_src) {
    unsigned saddr = (unsigned)__cvta_generic_to_shared(smem_dst);
    asm volatile("cp.async.ca.shared.global [%0], [%1], 4;\n"
                 :: "r"(saddr), "l"(gmem_src));
}
__device__ __forceinline__ void cp_commit() {
    asm volatile("cp.async.commit_group;\n" ::);
}
__device__ __forceinline__ void cp_wait1() {
    asm volatile("cp.async.wait_group 1;\n" ::: "memory");
}

// ---------------------------------------------------------------------------
// Kernel 1: per-row argmax / max + bbox decode + sort-key build. 1 warp/row.
// ---------------------------------------------------------------------------
__global__ void decode_kernel(const float* __restrict__ meta,
                              const float* __restrict__ deltas,
                              const float* __restrict__ proposals,
                              const float* __restrict__ scores) {
    int row  = (int)((blockIdx.x * blockDim.x + threadIdx.x) >> 5);
    int lane = threadIdx.x & 31;
    if (row >= NBOX) return;

    const float* srow = scores + (size_t)row * CLS;
    float best = -1.0f;
    int   bidx = 0x7FFFFFFF;
    float ms   = -1.0f;
    for (int j = lane; j < CLS; j += 32) {
        float v = srow[j];
        if (v > best) { best = v; bidx = j; }
        if (j >= 1) ms = fmaxf(ms, v);
    }
    #pragma unroll
    for (int off = 16; off; off >>= 1) {
        float ov = __shfl_down_sync(0xffffffffu, best, off);
        int   oi = __shfl_down_sync(0xffffffffu, bidx, off);
        float om = __shfl_down_sync(0xffffffffu, ms,   off);
        if (ov > best || (ov == best && oi < bidx)) { best = ov; bidx = oi; }
        ms = fmaxf(ms, om);
    }

    if (lane == 0) {
        float scale = meta[2];
        const float* p = proposals + (size_t)row * 4;
        float x1 = p[0] / scale, y1 = p[1] / scale;
        float x2 = p[2] / scale, y2 = p[3] / scale;
        float w  = x2 - x1 + 1.0f, h = y2 - y1 + 1.0f;
        float cx = x1 + 0.5f * w,  cy = y1 + 0.5f * h;

        const float* d = deltas + (size_t)row * (4 * CLS) + 4 * bidx;
        float pcx = d[0] * w + cx;
        float pcy = d[1] * h + cy;
        float pw  = expf(d[2]) * w;
        float ph  = expf(d[3]) * h;

        float W1 = meta[1] - 1.0f;
        float H1 = meta[0] - 1.0f;
        float ox1 = fminf(fmaxf(pcx - 0.5f * pw, 0.0f), W1);
        float oy1 = fminf(fmaxf(pcy - 0.5f * ph, 0.0f), H1);
        float ox2 = fminf(fmaxf(pcx + 0.5f * pw, 0.0f), W1);
        float oy2 = fminf(fmaxf(pcy + 0.5f * ph, 0.0f), H1);

        g_selv[row] = make_float4(ox1, oy1, ox2, oy2);
        unsigned int sb = __float_as_uint(ms);   // scores >= 0 -> monotonic bits
        g_key[row] = ((unsigned long long)sb << 13) |
                     (unsigned long long)(8191 - row);   // all keys distinct
    }
}

// ---------------------------------------------------------------------------
// Kernel 2: rank-by-counting + scatter into sorted order. 256 blocks.
// ---------------------------------------------------------------------------
__global__ void __launch_bounds__(256)
rank_kernel() {
    extern __shared__ unsigned long long keys[];   // 64 KB
    const int tid = threadIdx.x;
    for (int i = tid; i < NBOX; i += 256) keys[i] = g_key[i];
    __syncthreads();

    const int warp = tid >> 5, lane = tid & 31;
    const int row0 = blockIdx.x * 32 + warp * 4;

    unsigned long long rk0 = keys[row0 + 0];
    unsigned long long rk1 = keys[row0 + 1];
    unsigned long long rk2 = keys[row0 + 2];
    unsigned long long rk3 = keys[row0 + 3];
    int c0 = 0, c1 = 0, c2 = 0, c3 = 0;

    #pragma unroll 4
    for (int c = lane; c < NBOX; c += 32) {
        unsigned long long kc = keys[c];
        c0 += (kc > rk0);
        c1 += (kc > rk1);
        c2 += (kc > rk2);
        c3 += (kc > rk3);
    }
    #pragma unroll
    for (int off = 16; off; off >>= 1) {
        c0 += __shfl_down_sync(0xffffffffu, c0, off);
        c1 += __shfl_down_sync(0xffffffffu, c1, off);
        c2 += __shfl_down_sync(0xffffffffu, c2, off);
        c3 += __shfl_down_sync(0xffffffffu, c3, off);
    }
    if (lane == 0) {
        int rr[4] = {c0, c1, c2, c3};
        #pragma unroll
        for (int q = 0; q < 4; q++) {
            int i = row0 + q, r = rr[q];
            float4 b = g_selv[i];
            g_sbox[r]  = b;
            g_sarea[r] = fmaxf(b.z - b.x, 0.0f) * fmaxf(b.w - b.y, 0.0f);
            g_orig[r]  = i;
        }
    }
}

// ---------------------------------------------------------------------------
// Kernel 3: sorted-space IoU>0.5 bitmask, upper-triangle tiles only (1152).
// ---------------------------------------------------------------------------
__constant__ int c_prefix[9] = {0, 256, 480, 672, 832, 960, 1056, 1120, 1152};

__global__ void __launch_bounds__(256)
mask_kernel() {
    __shared__ float4 rbs[32];
    __shared__ float  ras[32];
    __shared__ float4 cbT[32 * 33];
    __shared__ float  caT[32 * 33];

    const int t = blockIdx.x;
    int g = 0;
    #pragma unroll
    for (int h = 1; h < 8; h++) g += (t >= c_prefix[h]);
    const int tp   = t - c_prefix[g];
    const int span = 8 - g;
    const int r    = tp / span;
    const int rb   = g * 32 + r;
    const int cb   = g + (tp - r * span);

    const int rowbase = rb * 32;
    const int colbase = cb * 1024;
    const int tid = threadIdx.x;

    if (tid < 32) {
        rbs[tid] = g_sbox[rowbase + tid];
        ras[tid] = g_sarea[rowbase + tid];
    }
    for (int jj = tid; jj < 1024; jj += 256) {
        int w = jj >> 5, bb = jj & 31;
        cbT[bb * 33 + w] = g_sbox[colbase + jj];
        caT[bb * 33 + w] = g_sarea[colbase + jj];
    }
    __syncthreads();

    const int r0 = tid >> 5;
    const int w  = tid & 31;
    float4 bi[4];
    float  si[4];
    #pragma unroll
    for (int k = 0; k < 4; k++) {
        bi[k] = rbs[r0 + 8 * k];
        si[k] = ras[r0 + 8 * k] + 1e-8f;
    }
    unsigned bits0 = 0, bits1 = 0, bits2 = 0, bits3 = 0;

    #pragma unroll
    for (int b = 0; b < 32; b++) {
        float4 bj = cbT[b * 33 + w];
        float  aj = caT[b * 33 + w];
        #pragma unroll
        for (int k = 0; k < 4; k++) {
            float xx1 = fmaxf(bi[k].x, bj.x), yy1 = fmaxf(bi[k].y, bj.y);
            float xx2 = fminf(bi[k].z, bj.z), yy2 = fminf(bi[k].w, bj.w);
            float iw  = fmaxf(xx2 - xx1, 0.0f);
            float ih  = fmaxf(yy2 - yy1, 0.0f);
            float inter = iw * ih;
            unsigned p = (3.0f * inter > si[k] + aj) ? (1u << b) : 0u;
            if (k == 0) bits0 |= p;
            else if (k == 1) bits1 |= p;
            else if (k == 2) bits2 |= p;
            else bits3 |= p;
        }
    }
    size_t base = (size_t)rowbase * NWORDS + (size_t)cb * 32 + w;
    g_masks[base + (size_t)(r0 +  0) * NWORDS] = bits0;
    g_masks[base + (size_t)(r0 +  8) * NWORDS] = bits1;
    g_masks[base + (size_t)(r0 + 16) * NWORDS] = bits2;
    g_masks[base + (size_t)(r0 + 24) * NWORDS] = bits3;
}

// ---------------------------------------------------------------------------
// Kernel 4: cp.async-pipelined greedy scan (R7 algebra, zero sync load-waits).
//  iter c: [bg: wait_group 1 ; apply staged keeps(c-3)] -> barrier ->
//          [t0: resolve chunk c from opring | bg: cp.async keeps(c-1) +
//           operands chunk c+2 ; commit]
//  sup_s lag = c-3 ; supfix = n1acc(c-1) | carry n2acc(c-2)   (verified R7)
// ---------------------------------------------------------------------------
__global__ void __launch_bounds__(256)
scan_kernel(const float* __restrict__ scores, float* __restrict__ out) {
    __shared__ unsigned           sup_s[NWORDS];            // 1 KB
    __shared__ unsigned long long opring[4][3][64];         // 6 KB
    __shared__ unsigned           stage[4][MAXK][NWORDS];   // 24 KB
    __shared__ unsigned long long ringkb[4];
    __shared__ unsigned long long kbuf[2];
    __shared__ int                kcnt[2];
    __shared__ int                s_keep[NPAD];

    const int tid = threadIdx.x;
    sup_s[tid] = 0u;
    if (tid == 0) {
        kbuf[0] = kbuf[1] = 0ull;
        kcnt[0] = kcnt[1] = 0;
        ringkb[0] = ringkb[1] = ringkb[2] = ringkb[3] = 0ull;
    }

    const unsigned long long* m64 = (const unsigned long long*)g_masks;
    const int e  = tid - 32;                          // bg task id 0..223
    const int w0 = e;                                 // owned word
    const int w1 = (e >= 0 && e < 32) ? e + 224 : -1; // second owned word

    // prologue: fill opring slots 0 and 1 synchronously
    if (tid >= 32 && e < 192) {
        int row = e & 63, f = e >> 6;                 // f: 0=conf 1=n1 2=n2
        opring[0][f][row] = __ldg(m64 + (size_t)row        * 128 + f);
        opring[1][f][row] = __ldg(m64 + (size_t)(64 + row) * 128 + 1 + f);
    }
    __syncthreads();

    unsigned long long supfix = 0ull, carry = 0ull;   // thread 0 only
    int nk_local = 0;                                 // thread 0 only

    for (int c = 0; c < NCH; c++) {
        // ---- pre-barrier: retire groups <= c-2, apply staged keeps(c-3) ----
        if (tid >= 32) {
            cp_wait1();
            if (c >= 3) {
                const int slot_a = (c - 2) & 3;
                unsigned long long ka = ringkb[slot_a];
                if (ka) {
                    unsigned acc0 = 0u, acc1 = 0u;
                    int s = 0;
                    while (ka) {
                        int l = __ffsll((long long)ka) - 1; ka &= ka - 1;
                        if (s < MAXK) {
                            acc0 |= stage[slot_a][s][w0];
                            if (w1 >= 0) acc1 |= stage[slot_a][s][w1];
                        } else {
                            const unsigned* row =
                                g_masks + (size_t)(64 * (c - 3) + l) * NWORDS;
                            acc0 |= __ldg(row + w0);
                            if (w1 >= 0) acc1 |= __ldg(row + w1);
                        }
                        s++;
                    }
                    if (acc0) sup_s[w0] |= acc0;
                    if (w1 >= 0 && acc1) sup_s[w1] |= acc1;
                }
            }
        }
        __syncthreads();
        if (c > 0 && kcnt[(c - 1) & 1] >= NPAD) break;   // uniform

        if (tid == 0) {
            // ---- resolution: pure smem ----
            const int slot = c & 3;
            unsigned long long sup64 =
                *(const unsigned long long*)&sup_s[2 * c];
            unsigned long long am = ~(sup64 | supfix);
            unsigned long long keepm = 0ull, n1acc = 0ull, n2acc = 0ull;
            int k2 = nk_local;
            while (am) {
                int l = __ffsll((long long)am) - 1;
                keepm |= 1ull << l;
                n1acc |= opring[slot][1][l];
                n2acc |= opring[slot][2][l];
                am &= ~opring[slot][0][l];
                am &= ~(1ull << l);
                if (k2 < NPAD) s_keep[k2++] = c * 64 + l;
            }
            kbuf[c & 1] = keepm;
            kcnt[c & 1] = k2;
            nk_local    = k2;
            supfix = carry | n1acc;
            carry  = n2acc;
        } else if (tid >= 32) {
            // ---- issue keep-row gathers for keeps(c-1) into stage[c&3] ----
            if (c >= 1) {
                unsigned long long km = kbuf[(c - 1) & 1];
                if (tid == 32) ringkb[c & 3] = km;
                int s = 0;
                while (km && s < MAXK) {
                    int l = __ffsll((long long)km) - 1; km &= km - 1;
                    const unsigned* row =
                        g_masks + (size_t)(64 * (c - 1) + l) * NWORDS;
                    cp_async4(&stage[c & 3][s][w0], row + w0);
                    if (w1 >= 0) cp_async4(&stage[c & 3][s][w1], row + w1);
                    s++;
                }
            }
            // ---- issue operand prefetch for chunk c+2 ----
            const int cf = c + 2;
            if (cf < NCH && e < 192) {
                int row = e & 63, f = e >> 6;
                int widx = cf + f; if (widx > 127) widx = 127;
                cp_async8(&opring[cf & 3][f][row],
                          m64 + (size_t)(64 * cf + row) * 128 + widx);
            }
            cp_commit();    // one group per bg thread per iteration
        }
    }
    __syncthreads();
    const int nk = (kcnt[0] > kcnt[1]) ? kcnt[0] : kcnt[1];

    // ---- outputs: boxes (300*4) then scores (300*81); zero invalid rows ----
    for (int idx = tid; idx < NPAD * 4; idx += 256) {
        int r = idx >> 2, cc = idx & 3;
        float v = 0.0f;
        if (r < nk) {
            float4 b = g_sbox[s_keep[r]];
            v = (cc == 0) ? b.x : (cc == 1) ? b.y : (cc == 2) ? b.z : b.w;
        }
        out[idx] = v;
    }
    for (int idx = tid; idx < NPAD * CLS; idx += 256) {
        int r = idx / CLS, cc = idx - r * CLS;
        float v = 0.0f;
        if (r < nk)
            v = scores[(size_t)g_orig[s_keep[r]] * CLS + cc];
        out[NPAD * 4 + idx] = v;
    }
}

// ---------------------------------------------------------------------------
extern "C" void kernel_launch(void* const* d_in, const int* in_sizes, int n_in,
                              void* d_out, int out_size) {
    const float* meta      = (const float*)d_in[0];
    const float* deltas    = (const float*)d_in[1];
    const float* proposals = (const float*)d_in[2];
    const float* scores    = (const float*)d_in[3];
    float* out = (float*)d_out;

    decode_kernel<<<NBOX / 8, 256>>>(meta, deltas, proposals, scores);

    cudaFuncSetAttribute(rank_kernel,
                         cudaFuncAttributeMaxDynamicSharedMemorySize, 65536);
    rank_kernel<<<256, 256, 65536>>>();

    mask_kernel<<<1152, 256>>>();

    scan_kernel<<<1, 256>>>(scores, out);
}